// round 14
// baseline (speedup 1.0000x reference)
#include <cuda_runtime.h>
#include <cstdint>

// B=128, T=1024, K=16, n=16, m=8, p=32
#define B_ 128
#define T_ 1024
#define TROW 20              // padded transposed-tile row stride (floats)
#define TSZ  336             // tile size: 16*20 + 16 gumbel (floats)

// Output layout (float32):
//  A_seq  (B,T,16,16) : [0,         33554432)
//  B_seq  (B,T,16,8)  : [33554432,  50331648)
//  C_seq  (B,1,32,16) : [50331648,  50397184)
//  log_q  (B,T)       : [50397184,  50528256)
//  log_p  (B,T)       : [50528256,  50659328)

__device__ __forceinline__ float frcp(float x) {
    float r; asm("rcp.approx.f32 %0, %1;" : "=f"(r) : "f"(x)); return r;
}
__device__ __forceinline__ float fex2(float x) {
    float r; asm("ex2.approx.f32 %0, %1;" : "=f"(r) : "f"(x)); return r;
}
__device__ __forceinline__ float flog(float x) {
    float r; asm("lg2.approx.f32 %0, %1;" : "=f"(r) : "f"(x)); return r * 0.6931471805599453f;
}

// ============================================================================
// Fused kernel, 1 block (320 thr = 10 warps) per chain. Software-pipelined on
// ONE uniform __syncthreads() per 16-step chunk (R11/R12-proven):
//   iter c: producers load+transpose chunk c | consumer computes chunk c-1
//           | mixers+stats process chunk c-2
// Warp->role map (SMSP = wid%4):
//   wid7 consumer (SMSP3)   wid3 stats-only (SMSP3, light)
//   wid 8,9 producers       wid 0,1,2,4,5,6 mixers (never SMSP3)
// Tiles stored TRANSPOSED with row stride 20: consumer column gather is
// 4 conflict-free LDS.128; next-step columns prefetched into registers.
// ============================================================================
__global__ __launch_bounds__(320, 1) void fused_kernel(
    const float* __restrict__ logits,   // (B,T,16,16)
    const float* __restrict__ gumbel,   // (B,T,16)
    const float* __restrict__ A,        // (16,16,16)
    const float* __restrict__ Bm,       // (16,16,8)
    const float* __restrict__ Cm,       // (16,32,16)
    const float* __restrict__ transP,   // (16,16)
    float* __restrict__ outA, float* __restrict__ outB, float* __restrict__ outC,
    float* __restrict__ outLQ, float* __restrict__ outLP)
{
    __shared__ __align__(16) float s_tileb[2][16 * TSZ]; // transposed chunk dbl-buf
    __shared__ __align__(16) float s_re [64 * 16];       // unnormalized e (4-chunk ring)
    __shared__ __align__(16) float s_rl [64 * 16];       // mixed logits l
    __shared__ __align__(16) float s_rw [64 * 16];       // (y_prev^T logP)_j
    __shared__ __align__(16) float s_rinv[64];           // 1/sum(e)
    __shared__ __align__(16) float s_logPT[16 * TROW];   // log transP TRANSPOSED [j*20+k]

    const int b    = blockIdx.x;
    const int tid  = threadIdx.x;
    const int wid  = tid >> 5;
    const int lane = tid & 31;
    const float KL    = 2.8853900817779268f;   // (2/tau)*log2(e), tau=0.5
    const float LOG2E = 1.4426950408889634f;

    if (wid == 0) {
        // transposed: s_logPT[j*TROW + k] = log P[k][j]
#pragma unroll
        for (int r = 0; r < 8; ++r) {
            const int idx = r * 32 + lane;          // 0..255
            const int k = idx >> 4, jj = idx & 15;
            s_logPT[jj * TROW + k] = flog(transP[idx]);
        }
    }
    __syncthreads();

    // ---------------- consumer state (wid7) ----------------
    const int  j  = lane & 15;
    const bool lo = lane < 16;
    float4 ev0 = make_float4(1.f, 1.f, 1.f, 1.f), ev1 = ev0, ev2 = ev0, ev3 = ev0;
    float inv = 0.0625f;
    float* rv = lo ? s_rl : s_rw;          // per-lane val destination

    // ---------------- producer state (wid 8,9) ----------------
    const int ptid = (wid - 8) * 32 + lane;               // 0..63 (valid wid>=8)
    const int pk   = ptid >> 2;                           // 0..15  (k row)
    const int pj0  = (ptid & 3) * 4;                      // 0,4,8,12 (j group)
    const float4* L4 = (const float4*)(logits + (size_t)b * (T_ * 256));
    const float4* G4 = (const float4*)(gumbel + (size_t)b * (T_ * 16));

    // ---------------- mixer state (wid 0,1,2,4,5,6) ----------------
    const int mi    = (wid < 3) ? wid : wid - 1;          // 0..5
    const int mtid  = mi * 32 + lane;                     // 0..191
    const int phase = mtid / 96;                          // 0/1 even/odd t
    const int q     = mtid % 96;                          // 0..63 A, 64..95 B
    float4 coef[16];
    if (wid < 7 && wid != 3) {
        if (q < 64) {
#pragma unroll
            for (int k = 0; k < 16; ++k) coef[k] = ((const float4*)A)[k * 64 + q];
        } else {
#pragma unroll
            for (int k = 0; k < 16; ++k) coef[k] = ((const float4*)Bm)[k * 32 + (q - 64)];
        }
    }
    float4* oA4 = (float4*)outA + (size_t)b * (1024 * 64);
    float4* oB4 = (float4*)outB + (size_t)b * (1024 * 32);

    // ---------------------------------------------------------------- pipeline
    for (int c = 0; c < 66; ++c) {
        if (wid == 7) {
            // ========== consumer: compute chunk c-1 ==========
            if (c >= 1 && c <= 64) {
                const int cc = c - 1;
                const float* tbase = s_tileb[cc & 1];
                // preload step-0 column + gumbel
                float4 L0, L1, L2, L3; float Kg;
                {
                    const float* bp = lo ? tbase : s_logPT;
                    const float4* p = (const float4*)(bp + j * TROW);
                    L0 = p[0]; L1 = p[1]; L2 = p[2]; L3 = p[3];
                    Kg = tbase[320 + j];
                }
#pragma unroll
                for (int i = 0; i < 16; ++i) {
                    float a0 = L0.x * ev0.x;
                    a0 = fmaf(L1.x, ev1.x, a0);
                    a0 = fmaf(L2.x, ev2.x, a0);
                    a0 = fmaf(L3.x, ev3.x, a0);
                    float a1 = L0.y * ev0.y;
                    a1 = fmaf(L1.y, ev1.y, a1);
                    a1 = fmaf(L2.y, ev2.y, a1);
                    a1 = fmaf(L3.y, ev3.y, a1);
                    float a2 = L0.z * ev0.z;
                    a2 = fmaf(L1.z, ev1.z, a2);
                    a2 = fmaf(L2.z, ev2.z, a2);
                    a2 = fmaf(L3.z, ev3.z, a2);
                    float a3 = L0.w * ev0.w;
                    a3 = fmaf(L1.w, ev1.w, a3);
                    a3 = fmaf(L2.w, ev2.w, a3);
                    a3 = fmaf(L3.w, ev3.w, a3);
                    const float lrw = (a0 + a1) + (a2 + a3);
                    // NOTE: column k maps to component: Lc[k] = L{k&3}.{x,y,z,w}[k>>2]
                    // layout: L0=(k=0,1,2,3) L1=(4,5,6,7) L2=(8,9,10,11) L3=(12,13,14,15)
                    // matvec pairs L0.x*e0.x etc. — e0..e3 hold e[0..3],[4..7],[8..11],[12..15]

                    const float val = lrw * inv;               // low: l_j, high: w_j
                    const float en  = fex2(fmaf(val, KL, Kg)); // exp((l+g)/tau)
                    const int rr = ((cc * 16 + i) & 63) * 16;
                    rv[rr + j] = val;                          // SIMT: s_rl / s_rw
                    if (lo) s_re[rr + j] = en;

                    // prefetch next step's column + gumbel (independent of exchange)
                    if (i < 15) {
                        const float* tb2 = tbase + (i + 1) * TSZ;
                        const float* bp2 = lo ? tb2 : s_logPT;
                        const float4* p2 = (const float4*)(bp2 + j * TROW);
                        L0 = p2[0]; L1 = p2[1]; L2 = p2[2]; L3 = p2[3];
                        Kg = tb2[320 + j];
                    }
                    __syncwarp();
                    const float4* ep = (const float4*)&s_re[rr];
                    ev0 = ep[0]; ev1 = ep[1]; ev2 = ep[2]; ev3 = ep[3];
                    float t0 = (ev0.x + ev0.y) + (ev0.z + ev0.w);
                    float t1 = (ev1.x + ev1.y) + (ev1.z + ev1.w);
                    float t2 = (ev2.x + ev2.y) + (ev2.z + ev2.w);
                    float t3 = (ev3.x + ev3.y) + (ev3.z + ev3.w);
                    inv = frcp((t0 + t1) + (t2 + t3));
                    if (lane == 0) s_rinv[(cc * 16 + i) & 63] = inv;
                }
            }
        } else if (wid >= 8) {
            // ========== producers: load chunk c, store TRANSPOSED ==========
            if (c < 64) {
                float* dstb = s_tileb[c & 1];
#pragma unroll
                for (int i = 0; i < 16; ++i) {
                    const float4 v = L4[(size_t)(c * 16 + i) * 64 + ptid];
                    float* dst = dstb + i * TSZ;
                    dst[(pj0 + 0) * TROW + pk] = v.x;
                    dst[(pj0 + 1) * TROW + pk] = v.y;
                    dst[(pj0 + 2) * TROW + pk] = v.z;
                    dst[(pj0 + 3) * TROW + pk] = v.w;
                }
                // gumbel: tile (ptid>>2), float4 group (ptid&3); pre-scaled by KL
                float4 g = G4[(size_t)(c * 16 + (ptid >> 2)) * 4 + (ptid & 3)];
                g.x *= KL; g.y *= KL; g.z *= KL; g.w *= KL;
                ((float4*)(dstb + (ptid >> 2) * TSZ + 320))[ptid & 3] = g;
            }
        } else if (wid == 3) {
            // ========== stats: lq/lp for chunk c-2; C_seq at c==0 ==========
            if (c == 0) {
                const float4* c4 = (const float4*)Cm;
                float4* o4 = (float4*)(outC + (size_t)b * 512);
#pragma unroll
                for (int r = 0; r < 4; ++r) o4[r * 32 + lane] = c4[r * 32 + lane];
            } else if (c >= 2 && lane < 16) {
                const int t  = (c - 2) * 16 + lane;
                const int rr = (t & 63) * 16;
                const float invt = s_rinv[t & 63];

                const float4* er = (const float4*)&s_re[rr];
                float4 e0 = er[0], e1 = er[1], e2 = er[2], e3 = er[3];
                const float4* lr = (const float4*)&s_rl[rr];
                float4 l0 = lr[0], l1 = lr[1], l2 = lr[2], l3 = lr[3];
                const float4* wr = (const float4*)&s_rw[rr];
                float4 w0 = wr[0], w1 = wr[1], w2 = wr[2], w3 = wr[3];

                float ev[16] = { e0.x,e0.y,e0.z,e0.w, e1.x,e1.y,e1.z,e1.w,
                                 e2.x,e2.y,e2.z,e2.w, e3.x,e3.y,e3.z,e3.w };
                float lv[16] = { l0.x,l0.y,l0.z,l0.w, l1.x,l1.y,l1.z,l1.w,
                                 l2.x,l2.y,l2.z,l2.w, l3.x,l3.y,l3.z,l3.w };
                float wv[16] = { w0.x,w0.y,w0.z,w0.w, w1.x,w1.y,w1.z,w1.w,
                                 w2.x,w2.y,w2.z,w2.w, w3.x,w3.y,w3.z,w3.w };

                float dot = 0.f, z = 0.f, lp = 0.f;
#pragma unroll
                for (int k = 0; k < 16; ++k) {
                    const float yk = ev[k] * invt;
                    dot = fmaf(yk, lv[k], dot);
                    lp  = fmaf(yk, wv[k], lp);
                    z  += fex2(lv[k] * LOG2E);       // exp(l) computed here now
                }
                const float lq = dot - flog(z);
                if (t == 0) lp = -2.7725887222397811f;   // -log(16)
                outLQ[(size_t)b * T_ + t] = lq;
                outLP[(size_t)b * T_ + t] = lp;
            }
        } else {
            // ========== mixers: A_seq/B_seq for chunk c-2 ==========
            if (c >= 2) {
#pragma unroll 2
                for (int i = 0; i < 8; ++i) {
                    const int t  = (c - 2) * 16 + 2 * i + phase;
                    const int rr = (t & 63) * 16;
                    const float4* yv = (const float4*)&s_re[rr];
                    const float4 e0 = yv[0], e1 = yv[1], e2 = yv[2], e3 = yv[3];
                    const float iv = s_rinv[t & 63];
                    float4 acc;
                    acc.x = e0.x * coef[0].x; acc.y = e0.x * coef[0].y;
                    acc.z = e0.x * coef[0].z; acc.w = e0.x * coef[0].w;
#define MIXK(kk, ee) \
                    acc.x = fmaf(ee, coef[kk].x, acc.x); acc.y = fmaf(ee, coef[kk].y, acc.y); \
                    acc.z = fmaf(ee, coef[kk].z, acc.z); acc.w = fmaf(ee, coef[kk].w, acc.w);
                    MIXK(1, e0.y)  MIXK(2, e0.z)  MIXK(3, e0.w)
                    MIXK(4, e1.x)  MIXK(5, e1.y)  MIXK(6, e1.z)  MIXK(7, e1.w)
                    MIXK(8, e2.x)  MIXK(9, e2.y)  MIXK(10, e2.z) MIXK(11, e2.w)
                    MIXK(12, e3.x) MIXK(13, e3.y) MIXK(14, e3.z) MIXK(15, e3.w)
#undef MIXK
                    acc.x *= iv; acc.y *= iv; acc.z *= iv; acc.w *= iv;
                    const size_t bt = (size_t)t;
                    if (q < 64) oA4[bt * 64 + q] = acc;
                    else        oB4[bt * 32 + (q - 64)] = acc;
                }
            }
        }
        __syncthreads();    // uniform, top-level: the only cross-warp sync
    }
}

extern "C" void kernel_launch(void* const* d_in, const int* in_sizes, int n_in,
                              void* d_out, int out_size)
{
    const float* logits = (const float*)d_in[0];
    const float* gumbel = (const float*)d_in[1];
    const float* A      = (const float*)d_in[2];
    const float* Bm     = (const float*)d_in[3];
    const float* Cm     = (const float*)d_in[4];
    const float* transP = (const float*)d_in[5];

    float* out   = (float*)d_out;
    float* outA  = out;
    float* outB  = out + (size_t)33554432;
    float* outC  = out + (size_t)50331648;
    float* outLQ = out + (size_t)50397184;
    float* outLP = out + (size_t)50528256;

    fused_kernel<<<B_, 320>>>(logits, gumbel, A, Bm, Cm, transP,
                              outA, outB, outC, outLQ, outLP);
}

// round 16
// speedup vs baseline: 1.4464x; 1.4464x over previous
#include <cuda_runtime.h>
#include <cstdint>

// B=128, T=1024, K=16, n=16, m=8, p=32
#define B_ 128
#define T_ 1024

// Output layout (float32):
//  A_seq  (B,T,16,16) : [0,         33554432)
//  B_seq  (B,T,16,8)  : [33554432,  50331648)
//  C_seq  (B,1,32,16) : [50331648,  50397184)
//  log_q  (B,T)       : [50397184,  50528256)
//  log_p  (B,T)       : [50528256,  50659328)

__device__ __forceinline__ float frcp(float x) {
    float r; asm("rcp.approx.f32 %0, %1;" : "=f"(r) : "f"(x)); return r;
}
__device__ __forceinline__ float fex2(float x) {
    float r; asm("ex2.approx.f32 %0, %1;" : "=f"(r) : "f"(x)); return r;
}
__device__ __forceinline__ float flog(float x) {
    float r; asm("lg2.approx.f32 %0, %1;" : "=f"(r) : "f"(x)); return r * 0.6931471805599453f;
}

// ============================================================================
// Fused kernel, 1 block (320 thr = 10 warps) per chain. Software-pipelined on
// ONE uniform __syncthreads() per 16-step chunk (R12-proven structure):
//   iter c: producers load chunk c | consumer computes chunk c-1
//           | mixers+stats process chunk c-2
// Warp->role map (SMSP = wid%4):
//   wid7 consumer (SMSP3)   wid3 stats-only (SMSP3, light)
//   wid 8,9 producers       wid 0,1,2,4,5,6 mixers (never SMSP3)
// R15 deltas vs R12 (consumer-only; producers untouched):
//   - next-step tile column prefetched into registers BEFORE __syncwarp
//   - exp(l) moved to stats warp; s_rel ring removed
// ============================================================================
__global__ __launch_bounds__(320, 1) void fused_kernel(
    const float* __restrict__ logits,   // (B,T,16,16)
    const float* __restrict__ gumbel,   // (B,T,16)
    const float* __restrict__ A,        // (16,16,16)
    const float* __restrict__ Bm,       // (16,16,8)
    const float* __restrict__ Cm,       // (16,32,16)
    const float* __restrict__ transP,   // (16,16)
    float* __restrict__ outA, float* __restrict__ outB, float* __restrict__ outC,
    float* __restrict__ outLQ, float* __restrict__ outLP)
{
    __shared__ __align__(16) float s_tileb[2][16 * 272]; // chunk tile dbl-buf (row-major)
    __shared__ __align__(16) float s_re [64 * 16];       // unnormalized e (4-chunk ring)
    __shared__ __align__(16) float s_rl [64 * 16];       // mixed logits l
    __shared__ __align__(16) float s_rw [64 * 16];       // (y_prev^T logP)_j
    __shared__ __align__(16) float s_rinv[64];           // 1/sum(e)
    __shared__ __align__(16) float s_logP[256];          // log transP [k*16+j]

    const int b    = blockIdx.x;
    const int tid  = threadIdx.x;
    const int wid  = tid >> 5;
    const int lane = tid & 31;
    const float KL    = 2.8853900817779268f;   // (2/tau)*log2(e), tau=0.5
    const float LOG2E = 1.4426950408889634f;

    if (wid == 0) {
#pragma unroll
        for (int r = 0; r < 8; ++r)
            s_logP[r * 32 + lane] = flog(transP[r * 32 + lane]);
    }
    __syncthreads();

    // ---------------- consumer state (wid7) ----------------
    const int  j  = lane & 15;
    const bool lo = lane < 16;
    float4 ev0 = make_float4(1.f, 1.f, 1.f, 1.f), ev1 = ev0, ev2 = ev0, ev3 = ev0;
    float inv = 0.0625f;
    float* rv = lo ? s_rl : s_rw;          // per-lane val destination

    // ---------------- producer state (wid 8,9) ----------------
    const int ptid = (wid - 8) * 32 + lane;               // 0..63 (valid wid>=8)
    const float4* L4 = (const float4*)(logits + (size_t)b * (T_ * 256));
    const float4* G4 = (const float4*)(gumbel + (size_t)b * (T_ * 16));

    // ---------------- mixer state (wid 0,1,2,4,5,6) ----------------
    const int mi    = (wid < 3) ? wid : wid - 1;          // 0..5
    const int mtid  = mi * 32 + lane;                     // 0..191
    const int phase = mtid / 96;                          // 0/1 even/odd t
    const int q     = mtid % 96;                          // 0..63 A, 64..95 B
    float4 coef[16];
    if (wid < 7 && wid != 3) {
        if (q < 64) {
#pragma unroll
            for (int k = 0; k < 16; ++k) coef[k] = ((const float4*)A)[k * 64 + q];
        } else {
#pragma unroll
            for (int k = 0; k < 16; ++k) coef[k] = ((const float4*)Bm)[k * 32 + (q - 64)];
        }
    }
    float4* oA4 = (float4*)outA + (size_t)b * (1024 * 64);
    float4* oB4 = (float4*)outB + (size_t)b * (1024 * 32);

    // ---------------------------------------------------------------- pipeline
    for (int c = 0; c < 66; ++c) {
        if (wid == 7) {
            // ========== consumer: compute chunk c-1 ==========
            if (c >= 1 && c <= 64) {
                const int cc = c - 1;
                const float* tbase = s_tileb[cc & 1];
                // preload step-0 column + gumbel
                float Lc[16]; float Kg;
                {
                    const float* bp = lo ? tbase : s_logP;
#pragma unroll
                    for (int k = 0; k < 16; ++k) Lc[k] = bp[k * 16 + j];
                    Kg = tbase[256 + j];
                }
#pragma unroll
                for (int i = 0; i < 16; ++i) {
                    float a0 = Lc[0] * ev0.x;
                    a0 = fmaf(Lc[4],  ev1.x, a0);
                    a0 = fmaf(Lc[8],  ev2.x, a0);
                    a0 = fmaf(Lc[12], ev3.x, a0);
                    float a1 = Lc[1] * ev0.y;
                    a1 = fmaf(Lc[5],  ev1.y, a1);
                    a1 = fmaf(Lc[9],  ev2.y, a1);
                    a1 = fmaf(Lc[13], ev3.y, a1);
                    float a2 = Lc[2] * ev0.z;
                    a2 = fmaf(Lc[6],  ev1.z, a2);
                    a2 = fmaf(Lc[10], ev2.z, a2);
                    a2 = fmaf(Lc[14], ev3.z, a2);
                    float a3 = Lc[3] * ev0.w;
                    a3 = fmaf(Lc[7],  ev1.w, a3);
                    a3 = fmaf(Lc[11], ev2.w, a3);
                    a3 = fmaf(Lc[15], ev3.w, a3);
                    const float lrw = (a0 + a1) + (a2 + a3);

                    const float val = lrw * inv;               // low: l_j, high: w_j
                    const float en  = fex2(fmaf(val, KL, Kg)); // exp((l+g)/tau)
                    const int rr = ((cc * 16 + i) & 63) * 16;
                    rv[rr + j] = val;                          // SIMT: s_rl / s_rw
                    if (lo) s_re[rr + j] = en;

                    // prefetch next step's column + gumbel (off the serial chain)
                    float Ln[16]; float Kgn;
                    if (i < 15) {
                        const float* tb2 = tbase + (i + 1) * 272;
                        const float* bp2 = lo ? tb2 : s_logP;
#pragma unroll
                        for (int k = 0; k < 16; ++k) Ln[k] = bp2[k * 16 + j];
                        Kgn = tb2[256 + j];
                    } else {
                        Kgn = 0.f;
#pragma unroll
                        for (int k = 0; k < 16; ++k) Ln[k] = 0.f;
                    }
                    __syncwarp();
                    const float4* ep = (const float4*)&s_re[rr];
                    ev0 = ep[0]; ev1 = ep[1]; ev2 = ep[2]; ev3 = ep[3];
                    float t0 = (ev0.x + ev0.y) + (ev0.z + ev0.w);
                    float t1 = (ev1.x + ev1.y) + (ev1.z + ev1.w);
                    float t2 = (ev2.x + ev2.y) + (ev2.z + ev2.w);
                    float t3 = (ev3.x + ev3.y) + (ev3.z + ev3.w);
                    inv = frcp((t0 + t1) + (t2 + t3));
                    if (lane == 0) s_rinv[(cc * 16 + i) & 63] = inv;
#pragma unroll
                    for (int k = 0; k < 16; ++k) Lc[k] = Ln[k];
                    Kg = Kgn;
                }
            }
        } else if (wid >= 8) {
            // ========== producers: load chunk c tiles into buf c&1 ==========
            if (c < 64) {
                float* dstb = s_tileb[c & 1];
#pragma unroll
                for (int i = 0; i < 16; ++i) {
                    ((float4*)(dstb + i * 272))[ptid] = L4[(size_t)(c * 16 + i) * 64 + ptid];
                }
                // gumbel: 16 rows x 4 float4 = 64 float4, one per producer lane
                float4 g = G4[(size_t)(c * 16 + (ptid >> 2)) * 4 + (ptid & 3)];
                g.x *= KL; g.y *= KL; g.z *= KL; g.w *= KL;
                ((float4*)(dstb + (ptid >> 2) * 272 + 256))[ptid & 3] = g;
            }
        } else if (wid == 3) {
            // ========== stats: lq/lp for chunk c-2; C_seq at c==0 ==========
            if (c == 0) {
                const float4* c4 = (const float4*)Cm;
                float4* o4 = (float4*)(outC + (size_t)b * 512);
#pragma unroll
                for (int r = 0; r < 4; ++r) o4[r * 32 + lane] = c4[r * 32 + lane];
            } else if (c >= 2 && lane < 16) {
                const int t  = (c - 2) * 16 + lane;
                const int rr = (t & 63) * 16;
                const float invt = s_rinv[t & 63];

                const float4* er = (const float4*)&s_re[rr];
                float4 e0 = er[0], e1 = er[1], e2 = er[2], e3 = er[3];
                const float4* lr = (const float4*)&s_rl[rr];
                float4 l0 = lr[0], l1 = lr[1], l2 = lr[2], l3 = lr[3];
                const float4* wr = (const float4*)&s_rw[rr];
                float4 w0 = wr[0], w1 = wr[1], w2 = wr[2], w3 = wr[3];

                float ev[16] = { e0.x,e0.y,e0.z,e0.w, e1.x,e1.y,e1.z,e1.w,
                                 e2.x,e2.y,e2.z,e2.w, e3.x,e3.y,e3.z,e3.w };
                float lv[16] = { l0.x,l0.y,l0.z,l0.w, l1.x,l1.y,l1.z,l1.w,
                                 l2.x,l2.y,l2.z,l2.w, l3.x,l3.y,l3.z,l3.w };
                float wv[16] = { w0.x,w0.y,w0.z,w0.w, w1.x,w1.y,w1.z,w1.w,
                                 w2.x,w2.y,w2.z,w2.w, w3.x,w3.y,w3.z,w3.w };

                float dot = 0.f, z = 0.f, lp = 0.f;
#pragma unroll
                for (int k = 0; k < 16; ++k) {
                    const float yk = ev[k] * invt;
                    dot = fmaf(yk, lv[k], dot);
                    lp  = fmaf(yk, wv[k], lp);
                    z  += fex2(lv[k] * LOG2E);       // exp(l) computed here
                }
                const float lq = dot - flog(z);
                if (t == 0) lp = -2.7725887222397811f;   // -log(16)
                outLQ[(size_t)b * T_ + t] = lq;
                outLP[(size_t)b * T_ + t] = lp;
            }
        } else {
            // ========== mixers: A_seq/B_seq for chunk c-2 ==========
            if (c >= 2) {
#pragma unroll 2
                for (int i = 0; i < 8; ++i) {
                    const int t  = (c - 2) * 16 + 2 * i + phase;
                    const int rr = (t & 63) * 16;
                    const float4* yv = (const float4*)&s_re[rr];
                    const float4 e0 = yv[0], e1 = yv[1], e2 = yv[2], e3 = yv[3];
                    const float iv = s_rinv[t & 63];
                    float4 acc;
                    acc.x = e0.x * coef[0].x; acc.y = e0.x * coef[0].y;
                    acc.z = e0.x * coef[0].z; acc.w = e0.x * coef[0].w;
#define MIXK(kk, ee) \
                    acc.x = fmaf(ee, coef[kk].x, acc.x); acc.y = fmaf(ee, coef[kk].y, acc.y); \
                    acc.z = fmaf(ee, coef[kk].z, acc.z); acc.w = fmaf(ee, coef[kk].w, acc.w);
                    MIXK(1, e0.y)  MIXK(2, e0.z)  MIXK(3, e0.w)
                    MIXK(4, e1.x)  MIXK(5, e1.y)  MIXK(6, e1.z)  MIXK(7, e1.w)
                    MIXK(8, e2.x)  MIXK(9, e2.y)  MIXK(10, e2.z) MIXK(11, e2.w)
                    MIXK(12, e3.x) MIXK(13, e3.y) MIXK(14, e3.z) MIXK(15, e3.w)
#undef MIXK
                    acc.x *= iv; acc.y *= iv; acc.z *= iv; acc.w *= iv;
                    const size_t bt = (size_t)t;
                    if (q < 64) oA4[bt * 64 + q] = acc;
                    else        oB4[bt * 32 + (q - 64)] = acc;
                }
            }
        }
        __syncthreads();    // uniform, top-level: the only cross-warp sync
    }
}

extern "C" void kernel_launch(void* const* d_in, const int* in_sizes, int n_in,
                              void* d_out, int out_size)
{
    const float* logits = (const float*)d_in[0];
    const float* gumbel = (const float*)d_in[1];
    const float* A      = (const float*)d_in[2];
    const float* Bm     = (const float*)d_in[3];
    const float* Cm     = (const float*)d_in[4];
    const float* transP = (const float*)d_in[5];

    float* out   = (float*)d_out;
    float* outA  = out;
    float* outB  = out + (size_t)33554432;
    float* outC  = out + (size_t)50331648;
    float* outLQ = out + (size_t)50397184;
    float* outLP = out + (size_t)50528256;

    fused_kernel<<<B_, 320>>>(logits, gumbel, A, Bm, Cm, transP,
                              outA, outB, outC, outLQ, outLP);
}